// round 4
// baseline (speedup 1.0000x reference)
#include <cuda_runtime.h>
#include <cstdint>
#include <cstddef>

// Problem constants
#define BATCH 32
#define SEQ   3136          // tokens N
#define DIM   384
#define HEADS 8
#define CH    48            // DIM / HEADS
#define QKVD  1152          // 3*DIM
#define GK    384           // GEMM K dim (both GEMMs have K=384)

// ---------------- scratch (device globals; no runtime allocation) ----------
__device__ float g_qkv [ (size_t)BATCH * SEQ * QKVD ];        // (B,N,1152)
__device__ float g_attn[ (size_t)BATCH * HEADS * CH * CH ];   // (B,H,48,48)
__device__ float g_weff[ (size_t)BATCH * DIM * DIM ];         // (B,384,384)

// ============================================================================
// Generic NT GEMM: C[m,n] = sum_k A[m,k]*B[n,k] (+bias[n])
// Tiles: 128x128x8, 256 threads, 8x8 per thread, double-buffered smem.
// Batched via blockIdx.z with element strides sA/sB/sC.
// ============================================================================
__global__ void __launch_bounds__(256, 2) gemm128_nt(
    const float* __restrict__ Ab, size_t sA, int lda,
    const float* __restrict__ Bb, size_t sB, int ldb,
    float*       __restrict__ Cb, size_t sC, int ldc,
    int M, const float* __restrict__ bias)
{
    __shared__ __align__(16) float As[2][8][132];
    __shared__ __align__(16) float Bs[2][8][132];

    const float* A = Ab + (size_t)blockIdx.z * sA;
    const float* B = Bb + (size_t)blockIdx.z * sB;
    float*       C = Cb + (size_t)blockIdx.z * sC;

    const int m0  = blockIdx.x << 7;
    const int n0  = blockIdx.y << 7;
    const int tid = threadIdx.x;

    // loader mapping: 2 threads per row, float4 each -> 128 rows x 8 k
    const int lr = tid >> 1;            // 0..127
    const int lk = (tid & 1) << 2;      // 0 or 4
    // compute mapping: 16x16 thread grid, 4+4 split rows/cols
    const int tx = tid & 15;
    const int ty = tid >> 4;

    const int  arow   = m0 + lr;
    const bool avalid = arow < M;
    const float* aptr = A + (size_t)arow * lda + lk;
    const float* bptr = B + (size_t)(n0 + lr) * ldb + lk;

    float acc[8][8];
#pragma unroll
    for (int i = 0; i < 8; ++i)
#pragma unroll
        for (int j = 0; j < 8; ++j) acc[i][j] = 0.f;

    const float4 f4z = make_float4(0.f, 0.f, 0.f, 0.f);

    // prologue: stage k-tile 0
    {
        float4 a4 = avalid ? *(const float4*)aptr : f4z;
        float4 b4 = *(const float4*)bptr;
        As[0][lk + 0][lr] = a4.x; As[0][lk + 1][lr] = a4.y;
        As[0][lk + 2][lr] = a4.z; As[0][lk + 3][lr] = a4.w;
        Bs[0][lk + 0][lr] = b4.x; Bs[0][lk + 1][lr] = b4.y;
        Bs[0][lk + 2][lr] = b4.z; Bs[0][lk + 3][lr] = b4.w;
    }
    __syncthreads();

    int buf = 0;
#pragma unroll 1
    for (int kt = 0; kt < GK / 8; ++kt) {
        float4 an = f4z, bn = f4z;
        const bool more = (kt + 1) < (GK / 8);
        if (more) {
            const float* ap = aptr + (kt + 1) * 8;
            const float* bp = bptr + (kt + 1) * 8;
            an = avalid ? *(const float4*)ap : f4z;
            bn = *(const float4*)bp;
        }

#pragma unroll
        for (int kk = 0; kk < 8; ++kk) {
            const float* Ak = &As[buf][kk][0];
            const float* Bk = &Bs[buf][kk][0];
            float4 a0 = *(const float4*)(Ak + (ty << 2));
            float4 a1 = *(const float4*)(Ak + (ty << 2) + 64);
            float4 b0 = *(const float4*)(Bk + (tx << 2));
            float4 b1 = *(const float4*)(Bk + (tx << 2) + 64);
            float ar[8] = {a0.x, a0.y, a0.z, a0.w, a1.x, a1.y, a1.z, a1.w};
            float br[8] = {b0.x, b0.y, b0.z, b0.w, b1.x, b1.y, b1.z, b1.w};
#pragma unroll
            for (int i = 0; i < 8; ++i)
#pragma unroll
                for (int j = 0; j < 8; ++j)
                    acc[i][j] = fmaf(ar[i], br[j], acc[i][j]);
        }

        if (more) {
            const int nb = buf ^ 1;
            As[nb][lk + 0][lr] = an.x; As[nb][lk + 1][lr] = an.y;
            As[nb][lk + 2][lr] = an.z; As[nb][lk + 3][lr] = an.w;
            Bs[nb][lk + 0][lr] = bn.x; Bs[nb][lk + 1][lr] = bn.y;
            Bs[nb][lk + 2][lr] = bn.z; Bs[nb][lk + 3][lr] = bn.w;
            __syncthreads();
            buf = nb;
        }
    }

    // epilogue
    float bv[8];
#pragma unroll
    for (int j = 0; j < 8; ++j) bv[j] = 0.f;
    if (bias) {
#pragma unroll
        for (int j = 0; j < 4; ++j) {
            bv[j]     = bias[n0 + (tx << 2) + j];
            bv[4 + j] = bias[n0 + (tx << 2) + 64 + j];
        }
    }
#pragma unroll
    for (int i = 0; i < 8; ++i) {
        const int r = m0 + (ty << 2) + ((i < 4) ? i : (60 + i));
        if (r < M) {
            float* crow = C + (size_t)r * ldc + n0 + (tx << 2);
            float4 v0 = make_float4(acc[i][0] + bv[0], acc[i][1] + bv[1],
                                    acc[i][2] + bv[2], acc[i][3] + bv[3]);
            float4 v1 = make_float4(acc[i][4] + bv[4], acc[i][5] + bv[5],
                                    acc[i][6] + bv[6], acc[i][7] + bv[7]);
            *(float4*)(crow)      = v0;
            *(float4*)(crow + 64) = v1;
        }
    }
}

// ============================================================================
// K2: per (b,h) — gram G = Q K^T over N tokens, plus sum-of-squares norms,
// then temperature scale + softmax over d. Writes attn (B,H,48,48).
// 256 threads as 16x16, 3x3 per thread, token tiles of 32, reg-prefetched.
// ============================================================================
__global__ void __launch_bounds__(256) xca_attn_kernel(
    const float* __restrict__ qkv,
    const float* __restrict__ temperature,
    float*       __restrict__ attn_out)
{
    const int bh = blockIdx.x;           // b*8 + h
    const int b  = bh >> 3;
    const int h  = bh & 7;
    const int tid = threadIdx.x;
    const int tx = tid & 15;
    const int ty = tid >> 4;

    __shared__ float qs[32][48];
    __shared__ float ks[32][48];
    __shared__ float Gs[48][49];
    __shared__ float sqq_s[48], sqk_s[48], nk_s[48];

    const float* qb = qkv + (size_t)b * SEQ * QKVD + h * CH;       // q slice
    const float* kb = qb + DIM;                                    // k slice

    int nls[6], css[6];
#pragma unroll
    for (int l = 0; l < 6; ++l) {
        int idx = l * 256 + tid;      // 0..1535 = 32*48
        nls[l] = idx / 48;
        css[l] = idx % 48;
    }

    float qr[6], kr[6];
#pragma unroll
    for (int l = 0; l < 6; ++l) {
        size_t off = (size_t)nls[l] * QKVD + css[l];
        qr[l] = qb[off];
        kr[l] = kb[off];
    }

    float a00 = 0, a01 = 0, a02 = 0, a10 = 0, a11 = 0, a12 = 0, a20 = 0, a21 = 0, a22 = 0;
    float sq0 = 0, sq1 = 0, sq2 = 0, sk0 = 0, sk1 = 0, sk2 = 0;

    const int NT = SEQ / 32;   // 98
#pragma unroll 1
    for (int t = 0; t < NT; ++t) {
        __syncthreads();
#pragma unroll
        for (int l = 0; l < 6; ++l) {
            qs[nls[l]][css[l]] = qr[l];
            ks[nls[l]][css[l]] = kr[l];
        }
        __syncthreads();

        if (t + 1 < NT) {
            const float* qn = qb + (size_t)(t + 1) * 32 * QKVD;
            const float* kn = kb + (size_t)(t + 1) * 32 * QKVD;
#pragma unroll
            for (int l = 0; l < 6; ++l) {
                size_t off = (size_t)nls[l] * QKVD + css[l];
                qr[l] = qn[off];
                kr[l] = kn[off];
            }
        }

#pragma unroll 2
        for (int nl = 0; nl < 32; ++nl) {
            float q0 = qs[nl][tx], q1 = qs[nl][tx + 16], q2 = qs[nl][tx + 32];
            float k0 = ks[nl][ty], k1 = ks[nl][ty + 16], k2 = ks[nl][ty + 32];
            a00 = fmaf(q0, k0, a00); a01 = fmaf(q0, k1, a01); a02 = fmaf(q0, k2, a02);
            a10 = fmaf(q1, k0, a10); a11 = fmaf(q1, k1, a11); a12 = fmaf(q1, k2, a12);
            a20 = fmaf(q2, k0, a20); a21 = fmaf(q2, k1, a21); a22 = fmaf(q2, k2, a22);
            if (ty == 0) {
                sq0 = fmaf(q0, q0, sq0); sq1 = fmaf(q1, q1, sq1); sq2 = fmaf(q2, q2, sq2);
            }
            if (tx == 0) {
                sk0 = fmaf(k0, k0, sk0); sk1 = fmaf(k1, k1, sk1); sk2 = fmaf(k2, k2, sk2);
            }
        }
    }

    __syncthreads();
    // deposit partial results: G[c][d], c = tx+16i, d = ty+16j
    Gs[tx     ][ty     ] = a00; Gs[tx     ][ty + 16] = a01; Gs[tx     ][ty + 32] = a02;
    Gs[tx + 16][ty     ] = a10; Gs[tx + 16][ty + 16] = a11; Gs[tx + 16][ty + 32] = a12;
    Gs[tx + 32][ty     ] = a20; Gs[tx + 32][ty + 16] = a21; Gs[tx + 32][ty + 32] = a22;
    if (ty == 0) { sqq_s[tx] = sq0; sqq_s[tx + 16] = sq1; sqq_s[tx + 32] = sq2; }
    if (tx == 0) { sqk_s[ty] = sk0; sqk_s[ty + 16] = sk1; sqk_s[ty + 32] = sk2; }
    __syncthreads();

    if (tid < 48) nk_s[tid] = fmaxf(sqrtf(sqk_s[tid]), 1e-12f);
    __syncthreads();

    if (tid < 48) {
        const int c = tid;
        const float scale = temperature[h] / fmaxf(sqrtf(sqq_s[c]), 1e-12f);
        float mx = -1e30f;
#pragma unroll
        for (int d = 0; d < 48; ++d) {
            float v = Gs[c][d] * scale / nk_s[d];
            Gs[c][d] = v;
            mx = fmaxf(mx, v);
        }
        float s = 0.f;
#pragma unroll
        for (int d = 0; d < 48; ++d) {
            float e = __expf(Gs[c][d] - mx);
            Gs[c][d] = e;
            s += e;
        }
        const float inv = 1.f / s;
        float* dst = attn_out + ((size_t)bh * 48 + c) * 48;
#pragma unroll
        for (int d = 0; d < 48; ++d) dst[d] = Gs[c][d] * inv;
    }
}

// ============================================================================
// K3: W_eff[b][e][h*48+d] = sum_c proj_w[e][h*48+c] * attn[b][h][c][d]
// One CTA per (b,h), 384 threads (one per e).
// ============================================================================
__global__ void __launch_bounds__(384) build_weff(
    const float* __restrict__ attn,
    const float* __restrict__ proj_w,
    float*       __restrict__ weff)
{
    const int bh = blockIdx.x;
    const int b  = bh >> 3;
    const int h  = bh & 7;
    const int tid = threadIdx.x;

    __shared__ float at[48][48];
    for (int i = tid; i < 48 * 48; i += 384)
        at[i / 48][i % 48] = attn[(size_t)bh * 2304 + i];
    __syncthreads();

    const int e = tid;
    float out[48];
#pragma unroll
    for (int d = 0; d < 48; ++d) out[d] = 0.f;

    const float* pw = proj_w + (size_t)e * DIM + h * CH;
#pragma unroll 4
    for (int c = 0; c < 48; ++c) {
        const float p = pw[c];
#pragma unroll
        for (int d = 0; d < 48; ++d) out[d] = fmaf(p, at[c][d], out[d]);
    }

    float* dst = weff + ((size_t)b * DIM + e) * DIM + h * CH;
#pragma unroll
    for (int d = 0; d < 48; ++d) dst[d] = out[d];
}

// ============================================================================
// host entry
// ============================================================================
extern "C" void kernel_launch(void* const* d_in, const int* in_sizes, int n_in,
                              void* d_out, int out_size)
{
    (void)in_sizes; (void)n_in; (void)out_size;
    const float* x      = (const float*)d_in[0];
    const float* qkv_w  = (const float*)d_in[1];
    const float* temp   = (const float*)d_in[2];
    const float* proj_w = (const float*)d_in[3];
    const float* proj_b = (const float*)d_in[4];
    float* out = (float*)d_out;

    float *qkv_p = nullptr, *attn_p = nullptr, *weff_p = nullptr;
    cudaGetSymbolAddress((void**)&qkv_p,  g_qkv);
    cudaGetSymbolAddress((void**)&attn_p, g_attn);
    cudaGetSymbolAddress((void**)&weff_p, g_weff);

    // K1: qkv = x @ qkv_w^T   (100352 x 1152, K=384)
    {
        dim3 grid((BATCH * SEQ) / 128, QKVD / 128, 1);
        gemm128_nt<<<grid, 256>>>(x, 0, DIM,
                                  qkv_w, 0, DIM,
                                  qkv_p, 0, QKVD,
                                  BATCH * SEQ, nullptr);
    }

    // K2: gram + norms + softmax -> attn  (one CTA per (b,h))
    xca_attn_kernel<<<BATCH * HEADS, 256>>>(qkv_p, temp, attn_p);

    // K3: W_eff[b] = proj_w @ blockdiag(attn_b)
    build_weff<<<BATCH * HEADS, 384>>>(attn_p, proj_w, weff_p);

    // K4: out[b] = v[b] @ W_eff[b]^T + proj_b   (batched, 3136 x 384, K=384)
    {
        dim3 grid((SEQ + 127) / 128, DIM / 128, BATCH);
        gemm128_nt<<<grid, 256>>>(qkv_p + 2 * DIM, (size_t)SEQ * QKVD, QKVD,
                                  weff_p,          (size_t)DIM * DIM,  DIM,
                                  out,             (size_t)SEQ * DIM,  DIM,
                                  SEQ, proj_b);
    }
}

// round 5
// speedup vs baseline: 1.0022x; 1.0022x over previous
#include <cuda_runtime.h>
#include <cstdint>
#include <cstddef>

// Problem constants
#define BATCH 32
#define SEQ   3136          // tokens N
#define DIM   384
#define HEADS 8
#define CH    48            // DIM / HEADS
#define QKVD  1152          // 3*DIM
#define GK    384           // GEMM K dim (both GEMMs have K=384)

// ---------------- scratch (device globals; no runtime allocation) ----------
__device__ float g_qkv [ (size_t)BATCH * SEQ * QKVD ];        // (B,N,1152)
__device__ float g_attn[ (size_t)BATCH * HEADS * CH * CH ];   // (B,H,48,48)
__device__ float g_weff[ (size_t)BATCH * DIM * DIM ];         // (B,384,384)

// ============================================================================
// Generic NT GEMM: C[m,n] = sum_k A[m,k]*B[n,k] (+bias[n])
// Tiles: 128x128x8, 256 threads, 8x8 per thread, double-buffered smem.
// Batched via blockIdx.z with element strides sA/sB/sC.
// ============================================================================
__global__ void __launch_bounds__(256, 2) gemm128_nt(
    const float* __restrict__ Ab, size_t sA, int lda,
    const float* __restrict__ Bb, size_t sB, int ldb,
    float*       __restrict__ Cb, size_t sC, int ldc,
    int M, const float* __restrict__ bias)
{
    __shared__ __align__(16) float As[2][8][132];
    __shared__ __align__(16) float Bs[2][8][132];

    const float* A = Ab + (size_t)blockIdx.z * sA;
    const float* B = Bb + (size_t)blockIdx.z * sB;
    float*       C = Cb + (size_t)blockIdx.z * sC;

    const int m0  = blockIdx.x << 7;
    const int n0  = blockIdx.y << 7;
    const int tid = threadIdx.x;

    // loader mapping: 2 threads per row, float4 each -> 128 rows x 8 k
    const int lr = tid >> 1;            // 0..127
    const int lk = (tid & 1) << 2;      // 0 or 4
    // compute mapping: 16x16 thread grid, 4+4 split rows/cols
    const int tx = tid & 15;
    const int ty = tid >> 4;

    const int  arow   = m0 + lr;
    const bool avalid = arow < M;
    const float* aptr = A + (size_t)arow * lda + lk;
    const float* bptr = B + (size_t)(n0 + lr) * ldb + lk;

    float acc[8][8];
#pragma unroll
    for (int i = 0; i < 8; ++i)
#pragma unroll
        for (int j = 0; j < 8; ++j) acc[i][j] = 0.f;

    const float4 f4z = make_float4(0.f, 0.f, 0.f, 0.f);

    // prologue: stage k-tile 0
    {
        float4 a4 = avalid ? *(const float4*)aptr : f4z;
        float4 b4 = *(const float4*)bptr;
        As[0][lk + 0][lr] = a4.x; As[0][lk + 1][lr] = a4.y;
        As[0][lk + 2][lr] = a4.z; As[0][lk + 3][lr] = a4.w;
        Bs[0][lk + 0][lr] = b4.x; Bs[0][lk + 1][lr] = b4.y;
        Bs[0][lk + 2][lr] = b4.z; Bs[0][lk + 3][lr] = b4.w;
    }
    __syncthreads();

    int buf = 0;
#pragma unroll 1
    for (int kt = 0; kt < GK / 8; ++kt) {
        float4 an = f4z, bn = f4z;
        const bool more = (kt + 1) < (GK / 8);
        if (more) {
            const float* ap = aptr + (kt + 1) * 8;
            const float* bp = bptr + (kt + 1) * 8;
            an = avalid ? *(const float4*)ap : f4z;
            bn = *(const float4*)bp;
        }

#pragma unroll
        for (int kk = 0; kk < 8; ++kk) {
            const float* Ak = &As[buf][kk][0];
            const float* Bk = &Bs[buf][kk][0];
            float4 a0 = *(const float4*)(Ak + (ty << 2));
            float4 a1 = *(const float4*)(Ak + (ty << 2) + 64);
            float4 b0 = *(const float4*)(Bk + (tx << 2));
            float4 b1 = *(const float4*)(Bk + (tx << 2) + 64);
            float ar[8] = {a0.x, a0.y, a0.z, a0.w, a1.x, a1.y, a1.z, a1.w};
            float br[8] = {b0.x, b0.y, b0.z, b0.w, b1.x, b1.y, b1.z, b1.w};
#pragma unroll
            for (int i = 0; i < 8; ++i)
#pragma unroll
                for (int j = 0; j < 8; ++j)
                    acc[i][j] = fmaf(ar[i], br[j], acc[i][j]);
        }

        if (more) {
            const int nb = buf ^ 1;
            As[nb][lk + 0][lr] = an.x; As[nb][lk + 1][lr] = an.y;
            As[nb][lk + 2][lr] = an.z; As[nb][lk + 3][lr] = an.w;
            Bs[nb][lk + 0][lr] = bn.x; Bs[nb][lk + 1][lr] = bn.y;
            Bs[nb][lk + 2][lr] = bn.z; Bs[nb][lk + 3][lr] = bn.w;
            __syncthreads();
            buf = nb;
        }
    }

    // epilogue
    float bv[8];
#pragma unroll
    for (int j = 0; j < 8; ++j) bv[j] = 0.f;
    if (bias) {
#pragma unroll
        for (int j = 0; j < 4; ++j) {
            bv[j]     = bias[n0 + (tx << 2) + j];
            bv[4 + j] = bias[n0 + (tx << 2) + 64 + j];
        }
    }
#pragma unroll
    for (int i = 0; i < 8; ++i) {
        const int r = m0 + (ty << 2) + ((i < 4) ? i : (60 + i));
        if (r < M) {
            float* crow = C + (size_t)r * ldc + n0 + (tx << 2);
            float4 v0 = make_float4(acc[i][0] + bv[0], acc[i][1] + bv[1],
                                    acc[i][2] + bv[2], acc[i][3] + bv[3]);
            float4 v1 = make_float4(acc[i][4] + bv[4], acc[i][5] + bv[5],
                                    acc[i][6] + bv[6], acc[i][7] + bv[7]);
            *(float4*)(crow)      = v0;
            *(float4*)(crow + 64) = v1;
        }
    }
}

// ============================================================================
// K2: per (b,h) — gram G = Q K^T over N tokens, plus sum-of-squares norms,
// then temperature scale + softmax over d. Writes attn (B,H,48,48).
// 256 threads as 16x16, 3x3 per thread, token tiles of 32, reg-prefetched.
// ============================================================================
__global__ void __launch_bounds__(256) xca_attn_kernel(
    const float* __restrict__ qkv,
    const float* __restrict__ temperature,
    float*       __restrict__ attn_out)
{
    const int bh = blockIdx.x;           // b*8 + h
    const int b  = bh >> 3;
    const int h  = bh & 7;
    const int tid = threadIdx.x;
    const int tx = tid & 15;
    const int ty = tid >> 4;

    __shared__ float qs[32][48];
    __shared__ float ks[32][48];
    __shared__ float Gs[48][49];
    __shared__ float sqq_s[48], sqk_s[48], nk_s[48];

    const float* qb = qkv + (size_t)b * SEQ * QKVD + h * CH;       // q slice
    const float* kb = qb + DIM;                                    // k slice

    int nls[6], css[6];
#pragma unroll
    for (int l = 0; l < 6; ++l) {
        int idx = l * 256 + tid;      // 0..1535 = 32*48
        nls[l] = idx / 48;
        css[l] = idx % 48;
    }

    float qr[6], kr[6];
#pragma unroll
    for (int l = 0; l < 6; ++l) {
        size_t off = (size_t)nls[l] * QKVD + css[l];
        qr[l] = qb[off];
        kr[l] = kb[off];
    }

    float a00 = 0, a01 = 0, a02 = 0, a10 = 0, a11 = 0, a12 = 0, a20 = 0, a21 = 0, a22 = 0;
    float sq0 = 0, sq1 = 0, sq2 = 0, sk0 = 0, sk1 = 0, sk2 = 0;

    const int NT = SEQ / 32;   // 98
#pragma unroll 1
    for (int t = 0; t < NT; ++t) {
        __syncthreads();
#pragma unroll
        for (int l = 0; l < 6; ++l) {
            qs[nls[l]][css[l]] = qr[l];
            ks[nls[l]][css[l]] = kr[l];
        }
        __syncthreads();

        if (t + 1 < NT) {
            const float* qn = qb + (size_t)(t + 1) * 32 * QKVD;
            const float* kn = kb + (size_t)(t + 1) * 32 * QKVD;
#pragma unroll
            for (int l = 0; l < 6; ++l) {
                size_t off = (size_t)nls[l] * QKVD + css[l];
                qr[l] = qn[off];
                kr[l] = kn[off];
            }
        }

#pragma unroll 2
        for (int nl = 0; nl < 32; ++nl) {
            float q0 = qs[nl][tx], q1 = qs[nl][tx + 16], q2 = qs[nl][tx + 32];
            float k0 = ks[nl][ty], k1 = ks[nl][ty + 16], k2 = ks[nl][ty + 32];
            a00 = fmaf(q0, k0, a00); a01 = fmaf(q0, k1, a01); a02 = fmaf(q0, k2, a02);
            a10 = fmaf(q1, k0, a10); a11 = fmaf(q1, k1, a11); a12 = fmaf(q1, k2, a12);
            a20 = fmaf(q2, k0, a20); a21 = fmaf(q2, k1, a21); a22 = fmaf(q2, k2, a22);
            if (ty == 0) {
                sq0 = fmaf(q0, q0, sq0); sq1 = fmaf(q1, q1, sq1); sq2 = fmaf(q2, q2, sq2);
            }
            if (tx == 0) {
                sk0 = fmaf(k0, k0, sk0); sk1 = fmaf(k1, k1, sk1); sk2 = fmaf(k2, k2, sk2);
            }
        }
    }

    __syncthreads();
    // deposit partial results: G[c][d], c = tx+16i, d = ty+16j
    Gs[tx     ][ty     ] = a00; Gs[tx     ][ty + 16] = a01; Gs[tx     ][ty + 32] = a02;
    Gs[tx + 16][ty     ] = a10; Gs[tx + 16][ty + 16] = a11; Gs[tx + 16][ty + 32] = a12;
    Gs[tx + 32][ty     ] = a20; Gs[tx + 32][ty + 16] = a21; Gs[tx + 32][ty + 32] = a22;
    if (ty == 0) { sqq_s[tx] = sq0; sqq_s[tx + 16] = sq1; sqq_s[tx + 32] = sq2; }
    if (tx == 0) { sqk_s[ty] = sk0; sqk_s[ty + 16] = sk1; sqk_s[ty + 32] = sk2; }
    __syncthreads();

    if (tid < 48) nk_s[tid] = fmaxf(sqrtf(sqk_s[tid]), 1e-12f);
    __syncthreads();

    if (tid < 48) {
        const int c = tid;
        const float scale = temperature[h] / fmaxf(sqrtf(sqq_s[c]), 1e-12f);
        float mx = -1e30f;
#pragma unroll
        for (int d = 0; d < 48; ++d) {
            float v = Gs[c][d] * scale / nk_s[d];
            Gs[c][d] = v;
            mx = fmaxf(mx, v);
        }
        float s = 0.f;
#pragma unroll
        for (int d = 0; d < 48; ++d) {
            float e = __expf(Gs[c][d] - mx);
            Gs[c][d] = e;
            s += e;
        }
        const float inv = 1.f / s;
        float* dst = attn_out + ((size_t)bh * 48 + c) * 48;
#pragma unroll
        for (int d = 0; d < 48; ++d) dst[d] = Gs[c][d] * inv;
    }
}

// ============================================================================
// K3: W_eff[b][e][h*48+d] = sum_c proj_w[e][h*48+c] * attn[b][h][c][d]
// One CTA per (b,h), 384 threads (one per e).
// ============================================================================
__global__ void __launch_bounds__(384) build_weff(
    const float* __restrict__ attn,
    const float* __restrict__ proj_w,
    float*       __restrict__ weff)
{
    const int bh = blockIdx.x;
    const int b  = bh >> 3;
    const int h  = bh & 7;
    const int tid = threadIdx.x;

    __shared__ float at[48][48];
    for (int i = tid; i < 48 * 48; i += 384)
        at[i / 48][i % 48] = attn[(size_t)bh * 2304 + i];
    __syncthreads();

    const int e = tid;
    float out[48];
#pragma unroll
    for (int d = 0; d < 48; ++d) out[d] = 0.f;

    const float* pw = proj_w + (size_t)e * DIM + h * CH;
#pragma unroll 4
    for (int c = 0; c < 48; ++c) {
        const float p = pw[c];
#pragma unroll
        for (int d = 0; d < 48; ++d) out[d] = fmaf(p, at[c][d], out[d]);
    }

    float* dst = weff + ((size_t)b * DIM + e) * DIM + h * CH;
#pragma unroll
    for (int d = 0; d < 48; ++d) dst[d] = out[d];
}

// ============================================================================
// host entry
// ============================================================================
extern "C" void kernel_launch(void* const* d_in, const int* in_sizes, int n_in,
                              void* d_out, int out_size)
{
    (void)in_sizes; (void)n_in; (void)out_size;
    const float* x      = (const float*)d_in[0];
    const float* qkv_w  = (const float*)d_in[1];
    const float* temp   = (const float*)d_in[2];
    const float* proj_w = (const float*)d_in[3];
    const float* proj_b = (const float*)d_in[4];
    float* out = (float*)d_out;

    float *qkv_p = nullptr, *attn_p = nullptr, *weff_p = nullptr;
    cudaGetSymbolAddress((void**)&qkv_p,  g_qkv);
    cudaGetSymbolAddress((void**)&attn_p, g_attn);
    cudaGetSymbolAddress((void**)&weff_p, g_weff);

    // K1: qkv = x @ qkv_w^T   (100352 x 1152, K=384)
    {
        dim3 grid((BATCH * SEQ) / 128, QKVD / 128, 1);
        gemm128_nt<<<grid, 256>>>(x, 0, DIM,
                                  qkv_w, 0, DIM,
                                  qkv_p, 0, QKVD,
                                  BATCH * SEQ, nullptr);
    }

    // K2: gram + norms + softmax -> attn  (one CTA per (b,h))
    xca_attn_kernel<<<BATCH * HEADS, 256>>>(qkv_p, temp, attn_p);

    // K3: W_eff[b] = proj_w @ blockdiag(attn_b)
    build_weff<<<BATCH * HEADS, 384>>>(attn_p, proj_w, weff_p);

    // K4: out[b] = v[b] @ W_eff[b]^T + proj_b   (batched, 3136 x 384, K=384)
    {
        dim3 grid((SEQ + 127) / 128, DIM / 128, BATCH);
        gemm128_nt<<<grid, 256>>>(qkv_p + 2 * DIM, (size_t)SEQ * QKVD, QKVD,
                                  weff_p,          (size_t)DIM * DIM,  DIM,
                                  out,             (size_t)SEQ * DIM,  DIM,
                                  SEQ, proj_b);
    }
}